// round 1
// baseline (speedup 1.0000x reference)
#include <cuda_runtime.h>
#include <cuda_bf16.h>
#include <math.h>

// Shapes (static per reference): x, x_r : (1, 3, 32, 512, 512) fp32
// size=64 -> hc=wc=32, nh=nw=16, patches per frame = 256, frames T=32.
// Patch elements = 3 * 32 * 32 = 3072. |(x+1)/2-(xr+1)/2| = |x-xr|/2.

#define T_FRAMES 32
#define C_CH     3
#define H_DIM    512
#define W_DIM    512
#define HC       32
#define WC       32
#define NPATCH_PER_FRAME 256   // 16 x 16
#define PATCH_ELEMS 3072       // C_CH * HC * WC

__device__ int g_frame_max[T_FRAMES];   // float bits, non-negative -> int atomicMax works

__global__ void init_kernel() {
    int t = threadIdx.x;
    if (t < T_FRAMES) g_frame_max[t] = 0;  // 0.0f bits == 0; also implements clamp at 0
}

__global__ __launch_bounds__(256) void patch_kernel(const float* __restrict__ x,
                                                    const float* __restrict__ xr) {
    // block = one patch
    int b  = blockIdx.x;                  // 0 .. 8191
    int t  = b >> 8;                      // frame
    int p  = b & 255;                     // patch within frame
    int ph = p >> 4;
    int pw = p & 15;
    int h0 = ph * HC;
    int w0 = pw * WC;
    int tid = threadIdx.x;

    float s = 0.0f;
    // 768 float4 per patch per tensor; 3 per thread
    #pragma unroll
    for (int i = 0; i < 3; i++) {
        int f   = tid + i * 256;          // float4 index in [0, 768)
        int c   = f >> 8;                 // channel
        int rem = f & 255;
        int row = rem >> 3;               // 0..31
        int col = rem & 7;                // float4 col 0..7
        long long base = (((long long)(c * T_FRAMES + t) * H_DIM + (h0 + row)) * W_DIM
                          + w0 + (col << 2));
        float4 a  = *(const float4*)(x  + base);
        float4 r  = *(const float4*)(xr + base);
        s += fabsf(a.x - r.x) + fabsf(a.y - r.y) + fabsf(a.z - r.z) + fabsf(a.w - r.w);
    }

    // warp reduce
    #pragma unroll
    for (int o = 16; o > 0; o >>= 1)
        s += __shfl_xor_sync(0xffffffffu, s, o);

    __shared__ float warp_sums[8];
    int lane = tid & 31, wid = tid >> 5;
    if (lane == 0) warp_sums[wid] = s;
    __syncthreads();

    if (wid == 0) {
        float v = (lane < 8) ? warp_sums[lane] : 0.0f;
        #pragma unroll
        for (int o = 4; o > 0; o >>= 1)
            v += __shfl_xor_sync(0xffffffffu, v, o);
        if (lane == 0) {
            // patch mean = sum / 3072 / 2
            float pm = v * (1.0f / 6144.0f);
            atomicMax(&g_frame_max[t], __float_as_int(pm));  // pm >= 0
        }
    }
}

__global__ void final_kernel(float* __restrict__ out) {
    int lane = threadIdx.x;
    float v = __int_as_float(g_frame_max[lane]);   // already >= 0 (init)
    #pragma unroll
    for (int o = 16; o > 0; o >>= 1)
        v += __shfl_xor_sync(0xffffffffu, v, o);
    if (lane == 0)
        out[0] = logf(v * (1.0f / (float)T_FRAMES));
}

extern "C" void kernel_launch(void* const* d_in, const int* in_sizes, int n_in,
                              void* d_out, int out_size) {
    const float* x  = (const float*)d_in[0];
    const float* xr = (const float*)d_in[1];
    float* out = (float*)d_out;

    init_kernel<<<1, 32>>>();
    patch_kernel<<<T_FRAMES * NPATCH_PER_FRAME, 256>>>(x, xr);
    final_kernel<<<1, 32>>>(out);
}

// round 2
// speedup vs baseline: 1.0221x; 1.0221x over previous
#include <cuda_runtime.h>
#include <cuda_bf16.h>
#include <math.h>

// x, x_r : (1, 3, 32, 512, 512) fp32. size=64 -> hc=wc=32, 16x16 patches/frame.
// |(x+1)/2-(xr+1)/2| = |x-xr|/2. Patch elems = 3*32*32 = 3072.

#define T_FRAMES 32
#define H_DIM    512
#define W_DIM    512
#define HC       32
#define WC       32
#define NBLOCKS  (T_FRAMES * 256)   // 8192: one block per patch

__device__ int g_frame_max[T_FRAMES] = {0};  // float bits; values >= 0 so int atomicMax OK
__device__ unsigned g_done = 0;

__global__ __launch_bounds__(256) void patch_kernel(const float* __restrict__ x,
                                                    const float* __restrict__ xr,
                                                    float* __restrict__ out) {
    int b  = blockIdx.x;                  // 0 .. 8191
    int t  = b >> 8;                      // frame
    int p  = b & 255;                     // patch within frame
    int h0 = (p >> 4) * HC;
    int w0 = (p & 15) * WC;
    int tid = threadIdx.x;

    float s = 0.0f;
    // 768 float4 per patch per tensor; 3 per thread, fully coalesced 128B rows
    #pragma unroll
    for (int i = 0; i < 3; i++) {
        int f   = tid + i * 256;          // float4 index in [0, 768)
        int c   = f >> 8;                 // channel
        int rem = f & 255;
        int row = rem >> 3;               // 0..31
        int col = rem & 7;                // float4 col 0..7
        long long base = (((long long)(c * T_FRAMES + t) * H_DIM + (h0 + row)) * W_DIM
                          + w0 + (col << 2));
        float4 a = *(const float4*)(x  + base);
        float4 r = *(const float4*)(xr + base);
        s += fabsf(a.x - r.x) + fabsf(a.y - r.y) + fabsf(a.z - r.z) + fabsf(a.w - r.w);
    }

    // warp reduce
    #pragma unroll
    for (int o = 16; o > 0; o >>= 1)
        s += __shfl_xor_sync(0xffffffffu, s, o);

    __shared__ float warp_sums[8];
    int lane = tid & 31, wid = tid >> 5;
    if (lane == 0) warp_sums[wid] = s;
    __syncthreads();

    if (wid == 0) {
        float v = (lane < 8) ? warp_sums[lane] : 0.0f;
        #pragma unroll
        for (int o = 4; o > 0; o >>= 1)
            v += __shfl_xor_sync(0xffffffffu, v, o);

        bool last = false;
        if (lane == 0) {
            float pm = v * (1.0f / 6144.0f);          // /3072 (mean) and /2
            atomicMax(&g_frame_max[t], __float_as_int(pm));
            __threadfence();
            unsigned prev = atomicAdd(&g_done, 1u);
            last = (prev == NBLOCKS - 1);
        }
        last = __shfl_sync(0xffffffffu, (int)last, 0);

        if (last) {
            // all atomicMax results are visible (threadfence + atomic ordering)
            float fm = __int_as_float(g_frame_max[lane]);   // lane -> frame, >= 0
            float sum = fm;
            #pragma unroll
            for (int o = 16; o > 0; o >>= 1)
                sum += __shfl_xor_sync(0xffffffffu, sum, o);
            if (lane == 0) {
                out[0] = logf(sum * (1.0f / (float)T_FRAMES));
                g_done = 0;                              // reset for next graph replay
            }
            g_frame_max[lane] = 0;                       // reset (also the clamp at 0)
        }
    }
}

extern "C" void kernel_launch(void* const* d_in, const int* in_sizes, int n_in,
                              void* d_out, int out_size) {
    const float* x  = (const float*)d_in[0];
    const float* xr = (const float*)d_in[1];
    patch_kernel<<<NBLOCKS, 256>>>(x, xr, (float*)d_out);
}